// round 8
// baseline (speedup 1.0000x reference)
#include <cuda_runtime.h>
#include <cuda_bf16.h>

#define DM   2048
#define DI   4096
#define MTOT 8192

// ---------------- scratch (device globals; runtime allocs forbidden) ------
__device__ __align__(128) __nv_bfloat16 g_xn  [(size_t)MTOT * DM];
__device__ __align__(128) __nv_bfloat16 g_win [(size_t)2 * DI * DM];
__device__ __align__(128) __nv_bfloat16 g_wout[(size_t)DM * DI];
__device__ __align__(128) __nv_bfloat16 g_h   [(size_t)MTOT * DI];
__device__ float g_dtw[DI];

// ---------------- helpers --------------------------------------------------
__device__ __forceinline__ unsigned smem_u32(const void* p) {
    unsigned a;
    asm("{ .reg .u64 t; cvta.to.shared.u64 t, %1; cvt.u32.u64 %0, t; }" : "=r"(a) : "l"(p));
    return a;
}
__device__ __forceinline__ void cp16(unsigned s, const void* g) {
    asm volatile("cp.async.cg.shared.global [%0], [%1], 16;" :: "r"(s), "l"(g));
}
#define CP_COMMIT() asm volatile("cp.async.commit_group;" ::: "memory")
#define CP_WAIT(n)  asm volatile("cp.async.wait_group %0;" :: "n"(n) : "memory")

#define SWZ(o) ((unsigned)(o) ^ ((((unsigned)(o)) >> 3) & 0x70u))

__device__ __forceinline__ void ldsm4(unsigned (&r)[4], unsigned a) {
    asm volatile("ldmatrix.sync.aligned.m8n8.x4.shared.b16 {%0,%1,%2,%3}, [%4];"
        : "=r"(r[0]), "=r"(r[1]), "=r"(r[2]), "=r"(r[3]) : "r"(a));
}
__device__ __forceinline__ void ldsm2(unsigned (&r)[2], unsigned a) {
    asm volatile("ldmatrix.sync.aligned.m8n8.x2.shared.b16 {%0,%1}, [%2];"
        : "=r"(r[0]), "=r"(r[1]) : "r"(a));
}
__device__ __forceinline__ void mma16816(float (&c)[4], const unsigned (&a)[4],
                                         const unsigned (&b)[2]) {
    asm volatile(
        "mma.sync.aligned.m16n8k16.row.col.f32.bf16.bf16.f32 "
        "{%0,%1,%2,%3}, {%4,%5,%6,%7}, {%8,%9}, {%0,%1,%2,%3};"
        : "+f"(c[0]), "+f"(c[1]), "+f"(c[2]), "+f"(c[3])
        : "r"(a[0]), "r"(a[1]), "r"(a[2]), "r"(a[3]), "r"(b[0]), "r"(b[1]));
}
__device__ __forceinline__ unsigned pk2(float a, float b) {
    __nv_bfloat162 t = __floats2bfloat162_rn(a, b);
    return *reinterpret_cast<unsigned*>(&t);
}
__device__ __forceinline__ float fsig(float v) {
    v = fminf(fmaxf(v, -15.f), 15.f);
    return 1.f / (1.f + __expf(-v));
}

// ---------------- prep kernels --------------------------------------------
__global__ void ln_kernel(const float* __restrict__ x,
                          const float* __restrict__ gamma,
                          const float* __restrict__ beta) {
    __shared__ float sred[16];
    __shared__ float s_mu, s_inv;
    int row = blockIdx.x, tid = threadIdx.x;
    const float4* xr = (const float4*)(x + (size_t)row * DM);
    float4 a = xr[tid], b = xr[tid + 256];
    float s = a.x + a.y + a.z + a.w + b.x + b.y + b.z + b.w;
    float q = a.x*a.x + a.y*a.y + a.z*a.z + a.w*a.w
            + b.x*b.x + b.y*b.y + b.z*b.z + b.w*b.w;
    for (int o = 16; o; o >>= 1) {
        s += __shfl_xor_sync(~0u, s, o);
        q += __shfl_xor_sync(~0u, q, o);
    }
    if ((tid & 31) == 0) { sred[tid >> 5] = s; sred[8 + (tid >> 5)] = q; }
    __syncthreads();
    if (tid == 0) {
        float S = 0.f, Q = 0.f;
        for (int i = 0; i < 8; i++) { S += sred[i]; Q += sred[8 + i]; }
        float mu = S / DM;
        s_mu = mu;
        s_inv = rsqrtf(Q / DM - mu * mu + 1e-5f);
    }
    __syncthreads();
    float mu = s_mu, inv = s_inv;
    float4 g0 = ((const float4*)gamma)[tid],       b0 = ((const float4*)beta)[tid];
    float4 g1 = ((const float4*)gamma)[tid + 256], b1 = ((const float4*)beta)[tid + 256];
    unsigned* dst = (unsigned*)(g_xn + (size_t)row * DM);
    float nx = (a.x - mu) * inv * g0.x + b0.x, ny = (a.y - mu) * inv * g0.y + b0.y;
    float nz = (a.z - mu) * inv * g0.z + b0.z, nw = (a.w - mu) * inv * g0.w + b0.w;
    dst[tid * 2]     = pk2(nx, ny);
    dst[tid * 2 + 1] = pk2(nz, nw);
    nx = (b.x - mu) * inv * g1.x + b1.x; ny = (b.y - mu) * inv * g1.y + b1.y;
    nz = (b.z - mu) * inv * g1.z + b1.z; nw = (b.w - mu) * inv * g1.w + b1.w;
    dst[(tid + 256) * 2]     = pk2(nx, ny);
    dst[(tid + 256) * 2 + 1] = pk2(nz, nw);
}

__global__ void cvt_kernel(const float* __restrict__ src, int which, int n4) {
    __nv_bfloat16* dst = which ? g_win : g_wout;
    int i = blockIdx.x * blockDim.x + threadIdx.x;
    if (i < n4) {
        float4 f = ((const float4*)src)[i];
        uint2 o;
        o.x = pk2(f.x, f.y);
        o.y = pk2(f.z, f.w);
        ((uint2*)dst)[i] = o;
    }
}

__global__ void dts_kernel(const float* __restrict__ dt) {
    __shared__ float red[32];
    __shared__ float s_m, s_s;
    int tid = threadIdx.x;
    float m = -1e30f;
    for (int i = tid; i < DI; i += 1024) m = fmaxf(m, -dt[i]);
    for (int o = 16; o; o >>= 1) m = fmaxf(m, __shfl_xor_sync(~0u, m, o));
    if ((tid & 31) == 0) red[tid >> 5] = m;
    __syncthreads();
    if (tid == 0) {
        float M = -1e30f;
        for (int i = 0; i < 32; i++) M = fmaxf(M, red[i]);
        s_m = M;
    }
    __syncthreads();
    float M = s_m, s = 0.f;
    for (int i = tid; i < DI; i += 1024) s += __expf(-dt[i] - M);
    for (int o = 16; o; o >>= 1) s += __shfl_xor_sync(~0u, s, o);
    if ((tid & 31) == 0) red[tid >> 5] = s;
    __syncthreads();
    if (tid == 0) {
        float S = 0.f;
        for (int i = 0; i < 32; i++) S += red[i];
        s_s = S;
    }
    __syncthreads();
    float inv = 1.f / s_s;
    for (int i = tid; i < DI; i += 1024) g_dtw[i] = __expf(-dt[i] - M) * inv;
}

// ---------------- mma.sync GEMMs ------------------------------------------
// Shared tile layout: every tile row is 64 bf16 = 128 bytes (SW128 swizzle).
// Stage (both kernels) = 32 KB:
//   FUSED:  A[128x64] @0, Bz[64x64] @16K, Bg[64x64] @24K
//   !FUSED: A[128x64] @0, B[128x64] @16K
// 3 stages, cp.async pipeline.

#define NSTAGE 3
#define STAGEB 32768u

// FUSED=true : h[128 x 64]-tile = z*sig(clamp z)*dtw * gate_c*sig(gate_c)
// FUSED=false: out[128 x 128]-tile = h @ W_out^T + x
template <bool FUSED>
__global__ void __launch_bounds__(256)
gemm_kernel(const float* __restrict__ xres, float* __restrict__ out) {
    extern __shared__ char smem[];
    const unsigned sbase = smem_u32(smem);
    __shared__ float s_dtw[64];

    const int tid = threadIdx.x, wid = tid >> 5, lane = tid & 31;
    const int wm = wid & 1;          // 2 warp-rows  (64 M each)
    const int wn = wid >> 1;         // 4 warp-cols
    const int m0 = blockIdx.y * 128;
    const int n0 = blockIdx.x * (FUSED ? 64 : 128);
    const int KIT = FUSED ? (DM / 64) : (DI / 64);
    const int ldA = FUSED ? DM : DI;
    const __nv_bfloat16* A  = FUSED ? g_xn : g_h;
    const __nv_bfloat16* B0 = FUSED ? g_win : g_wout;
    const __nv_bfloat16* B1 = g_win + (size_t)DI * DM;      // gate half

    if (FUSED && tid < 64) s_dtw[tid] = g_dtw[n0 + tid];

    const int NT = FUSED ? 2 : 4;    // n-tiles (8 wide) per warp
    float acc0[4][4][4];             // z (or out)
    float acc1[4][2][4];             // gate (fused only)
    #pragma unroll
    for (int mt = 0; mt < 4; mt++)
        #pragma unroll
        for (int nt = 0; nt < 4; nt++)
            #pragma unroll
            for (int j = 0; j < 4; j++) acc0[mt][nt][j] = 0.f;
    if (FUSED)
        #pragma unroll
        for (int mt = 0; mt < 4; mt++)
            #pragma unroll
            for (int nt = 0; nt < 2; nt++)
                #pragma unroll
                for (int j = 0; j < 4; j++) acc1[mt][nt][j] = 0.f;

    auto load_stage = [&](int s, int kb) {
        unsigned sb = sbase + (unsigned)s * STAGEB;
        int k0 = kb * 64;
        #pragma unroll
        for (int i = tid; i < 2048; i += 256) {
            if (FUSED) {
                if (i < 1024) {            // A 128 rows
                    int r = i >> 3, c = i & 7;
                    cp16(sb + SWZ(r * 128 + c * 16),
                         A + (size_t)(m0 + r) * ldA + k0 + c * 8);
                } else if (i < 1536) {     // Bz 64 rows
                    int j = i - 1024, r = j >> 3, c = j & 7;
                    cp16(sb + 16384u + SWZ(r * 128 + c * 16),
                         B0 + (size_t)(n0 + r) * DM + k0 + c * 8);
                } else {                   // Bg 64 rows
                    int j = i - 1536, r = j >> 3, c = j & 7;
                    cp16(sb + 24576u + SWZ(r * 128 + c * 16),
                         B1 + (size_t)(n0 + r) * DM + k0 + c * 8);
                }
            } else {
                if (i < 1024) {            // A 128 rows
                    int r = i >> 3, c = i & 7;
                    cp16(sb + SWZ(r * 128 + c * 16),
                         A + (size_t)(m0 + r) * ldA + k0 + c * 8);
                } else {                   // B 128 rows
                    int j = i - 1024, r = j >> 3, c = j & 7;
                    cp16(sb + 16384u + SWZ(r * 128 + c * 16),
                         B0 + (size_t)(n0 + r) * DI + k0 + c * 8);
                }
            }
        }
        CP_COMMIT();
    };

    load_stage(0, 0);
    load_stage(1, 1);

    // per-lane ldmatrix address components
    const int arow = (lane & 7) + (lane & 8);        // 0..15
    const unsigned acsel = (lane >> 4) ? 16u : 0u;   // k-half select (bytes)
    const int brow = lane & 7;
    const unsigned bcsel = (lane & 8) ? 16u : 0u;

    for (int kb = 0; kb < KIT; kb++) {
        if (kb == KIT - 1) { CP_WAIT(0); } else { CP_WAIT(1); }
        __syncthreads();
        if (kb + 2 < KIT) load_stage((kb + 2) % NSTAGE, kb + 2);

        unsigned sb = sbase + (unsigned)(kb % NSTAGE) * STAGEB;
        unsigned sBz = sb + 16384u;
        unsigned sBg = sb + 24576u;
        #pragma unroll
        for (int kc = 0; kc < 4; kc++) {
            unsigned a[4][4];
            #pragma unroll
            for (int mt = 0; mt < 4; mt++)
                ldsm4(a[mt], sb + SWZ((unsigned)((wm * 64 + mt * 16 + arow) * 128
                                                 + kc * 32) + acsel));
            if (FUSED) {
                #pragma unroll
                for (int nt = 0; nt < 2; nt++) {
                    unsigned bz[2], bg[2];
                    unsigned roff = (unsigned)((wn * 16 + nt * 8 + brow) * 128 + kc * 32);
                    ldsm2(bz, sBz + SWZ(roff + bcsel));
                    ldsm2(bg, sBg + SWZ(roff + bcsel));
                    #pragma unroll
                    for (int mt = 0; mt < 4; mt++) {
                        mma16816(acc0[mt][nt], a[mt], bz);
                        mma16816(acc1[mt][nt], a[mt], bg);
                    }
                }
            } else {
                #pragma unroll
                for (int nt = 0; nt < 4; nt++) {
                    unsigned b[2];
                    unsigned roff = (unsigned)((wn * 32 + nt * 8 + brow) * 128 + kc * 32);
                    ldsm2(b, sBz + SWZ(roff + bcsel));
                    #pragma unroll
                    for (int mt = 0; mt < 4; mt++)
                        mma16816(acc0[mt][nt], a[mt], b);
                }
            }
        }
        __syncthreads();
    }

    // ---------------- epilogue ---------------------------------------------
    const int mrow = (lane >> 2);
    const int ncol = (lane & 3) * 2;
    if (FUSED) {
        #pragma unroll
        for (int mt = 0; mt < 4; mt++)
            #pragma unroll
            for (int nt = 0; nt < 2; nt++) {
                int nl = wn * 16 + nt * 8 + ncol;
                float w0 = s_dtw[nl], w1 = s_dtw[nl + 1];
                #pragma unroll
                for (int h = 0; h < 2; h++) {
                    int m = m0 + wm * 64 + mt * 16 + mrow + h * 8;
                    float z0 = acc0[mt][nt][h * 2], z1 = acc0[mt][nt][h * 2 + 1];
                    float q0 = acc1[mt][nt][h * 2], q1 = acc1[mt][nt][h * 2 + 1];
                    float gc0 = fminf(fmaxf(q0, -15.f), 15.f);
                    float gc1 = fminf(fmaxf(q1, -15.f), 15.f);
                    float v0 = z0 * fsig(z0) * w0 * gc0 * fsig(gc0);
                    float v1 = z1 * fsig(z1) * w1 * gc1 * fsig(gc1);
                    *(unsigned*)(g_h + (size_t)m * DI + n0 + nl) = pk2(v0, v1);
                }
            }
    } else {
        #pragma unroll
        for (int mt = 0; mt < 4; mt++)
            #pragma unroll
            for (int nt = 0; nt < 4; nt++) {
                int n = n0 + wn * 32 + nt * 8 + ncol;
                #pragma unroll
                for (int h = 0; h < 2; h++) {
                    int m = m0 + wm * 64 + mt * 16 + mrow + h * 8;
                    const float2 xv = *(const float2*)(xres + (size_t)m * DM + n);
                    float2 o;
                    o.x = acc0[mt][nt][h * 2]     + xv.x;
                    o.y = acc0[mt][nt][h * 2 + 1] + xv.y;
                    *(float2*)(out + (size_t)m * DM + n) = o;
                }
            }
    }
}

// ---------------- launch ----------------------------------------------------
extern "C" void kernel_launch(void* const* d_in, const int* in_sizes, int n_in,
                              void* d_out, int out_size) {
    const float* x     = (const float*)d_in[0];
    const float* gamma = (const float*)d_in[1];
    const float* beta  = (const float*)d_in[2];
    const float* W_in  = (const float*)d_in[3];
    const float* W_out = (const float*)d_in[4];
    const float* dt    = (const float*)d_in[5];
    float* out = (float*)d_out;

    ln_kernel<<<MTOT, 256>>>(x, gamma, beta);
    {
        int n4 = 2 * DI * DM / 4;
        cvt_kernel<<<(n4 + 255) / 256, 256>>>(W_in, 1, n4);
    }
    {
        int n4 = DM * DI / 4;
        cvt_kernel<<<(n4 + 255) / 256, 256>>>(W_out, 0, n4);
    }
    dts_kernel<<<1, 1024>>>(dt);

    const unsigned smem = NSTAGE * STAGEB;   // 96 KB
    static int attr_done = 0;
    if (!attr_done) {
        cudaFuncSetAttribute(gemm_kernel<true>,
                             cudaFuncAttributeMaxDynamicSharedMemorySize, smem);
        cudaFuncSetAttribute(gemm_kernel<false>,
                             cudaFuncAttributeMaxDynamicSharedMemorySize, smem);
        attr_done = 1;
    }
    gemm_kernel<true ><<<dim3(DI / 64, MTOT / 128), 256, smem>>>(nullptr, nullptr);
    gemm_kernel<false><<<dim3(DM / 128, MTOT / 128), 256, smem>>>(x, out);
}